// round 13
// baseline (speedup 1.0000x reference)
#include <cuda_runtime.h>
#include <cuda_fp16.h>
#include <math.h>
#include <stdint.h>

#define H    1024
#define H3   3072
#define NREL 4096
#define NATT 4096
#define NCL  8192
#define V    256

// ===================== scratch (device globals; no allocations) =====================
__device__ __align__(256) __half g2_table[V * H];
__device__ __align__(256) __half g2_Wemb[H * H];
__device__ __align__(256) __half g2_Wih[H3 * H];
__device__ __align__(256) __half g2_Whh[H3 * H];
__device__ __align__(256) __half g2_W1[H * H];
__device__ __align__(256) __half g2_W2[H * H];
__device__ __align__(256) __half g2_emb[V * H];
__device__ __align__(256) __half g2_h1[V * H];
__device__ __align__(256) __half g2_h2rel[NREL * H];
__device__ __align__(256) __half g2_clause[NCL * H];
__device__ __align__(256) __half g2_x1[NCL * H];
__device__ __align__(256) __half g2_gi[V * H3];
__device__ __align__(256) __half g2_gh2[V * H3];
__device__ __align__(256) __half g2_gh3[NREL * H3];
__device__ float g_gh1[H3];
__device__ float g_lpart[NCL * 16];

// ===================== PTX helpers =====================
__device__ __forceinline__ uint32_t smem_u32(const void* p) {
    uint32_t a;
    asm("{ .reg .u64 t; cvta.to.shared.u64 t, %1; cvt.u32.u64 %0, t; }" : "=r"(a) : "l"(p));
    return a;
}
__device__ __forceinline__ void cp16(uint32_t dst, const void* src) {
    asm volatile("cp.async.cg.shared.global [%0], [%1], 16;" :: "r"(dst), "l"(src));
}
__device__ __forceinline__ void cp_commit() {
    asm volatile("cp.async.commit_group;" ::: "memory");
}
template <int N>
__device__ __forceinline__ void cp_wait() {
    asm volatile("cp.async.wait_group %0;" :: "n"(N) : "memory");
}
__device__ __forceinline__ void ldm_x4(uint32_t& r0, uint32_t& r1, uint32_t& r2, uint32_t& r3,
                                       uint32_t addr) {
    asm volatile("ldmatrix.sync.aligned.m8n8.x4.shared.b16 {%0,%1,%2,%3}, [%4];"
                 : "=r"(r0), "=r"(r1), "=r"(r2), "=r"(r3) : "r"(addr));
}
__device__ __forceinline__ void mma16816(float* c, uint32_t a0, uint32_t a1, uint32_t a2,
                                         uint32_t a3, uint32_t b0, uint32_t b1) {
    asm volatile(
        "mma.sync.aligned.m16n8k16.row.col.f32.f16.f16.f32 "
        "{%0,%1,%2,%3}, {%4,%5,%6,%7}, {%8,%9}, {%0,%1,%2,%3};"
        : "+f"(c[0]), "+f"(c[1]), "+f"(c[2]), "+f"(c[3])
        : "r"(a0), "r"(a1), "r"(a2), "r"(a3), "r"(b0), "r"(b1));
}
__device__ __forceinline__ float tanh_fast(float x) {
    float y;
    asm("tanh.approx.f32 %0, %1;" : "=f"(y) : "f"(x));
    return y;
}

// fp32 row -> fp16 row (256 threads, 4 elems each)
__device__ __forceinline__ void cvt_row(const float* __restrict__ src,
                                        __half* __restrict__ dst, int r, int tid)
{
    int c4 = tid * 4;
    float4 x = *(const float4*)(src + (size_t)r * H + c4);
    __half* o = dst + (size_t)r * H + c4;
    *(__half2*)(o)     = __halves2half2(__float2half(x.x), __float2half(x.y));
    *(__half2*)(o + 2) = __halves2half2(__float2half(x.z), __float2half(x.w));
}

#define APITCH   80
#define NIT      32

// ===================== shared 128x128 fp16 HMMA body ====================
#define ATILE_B  (128 * APITCH)
#define STAGE_B  (2 * ATILE_B)
#define SMEM_DYN_H (4 * STAGE_B)        // 81920

__device__ __forceinline__ void cp_stage(const __half* __restrict__ A,
                                         const __half* __restrict__ B,
                                         int bm, int bn, uint32_t sbase, int tid,
                                         int it)
{
    const int kk = it * 32;
#pragma unroll
    for (int h = 0; h < 2; h++) {
        int c = tid + h * 256;
        int row = c >> 2, kc = c & 3;
        cp16(sbase + row * APITCH + kc * 16,
             A + (size_t)(bm + row) * H + kk + kc * 8);
    }
#pragma unroll
    for (int h = 0; h < 2; h++) {
        int c = tid + h * 256;
        int row = c >> 2, kc = c & 3;
        cp16(sbase + ATILE_B + row * APITCH + kc * 16,
             B + (size_t)(bn + row) * H + kk + kc * 8);
    }
}

template <bool RELU, bool OUTS, bool LOGITS>
__device__ __forceinline__ void body128(
    const __half* __restrict__ A, const __half* __restrict__ B,
    const float* __restrict__ bias, __half* __restrict__ Cs, int N,
    int bm, int bn,
    const float* __restrict__ w3, float* __restrict__ lpart, int bxLog,
    uint32_t sbase, int tid)
{
    const int lane = tid & 31, w = tid >> 5;
    const int wm = w & 3, wn = w >> 2;

#pragma unroll
    for (int s = 0; s < 3; s++) {
        cp_stage(A, B, bm, bn, sbase + s * STAGE_B, tid, s);
        cp_commit();
    }

    float acc[2][8][4];
#pragma unroll
    for (int mb = 0; mb < 2; mb++)
#pragma unroll
        for (int nb = 0; nb < 8; nb++)
#pragma unroll
            for (int q = 0; q < 4; q++) acc[mb][nb][q] = 0.f;

    const int quad = lane >> 3, li = lane & 7;
    const uint32_t aAddr = sbase +
        (uint32_t)((wm * 32 + (quad & 1) * 8 + li) * APITCH + (quad >> 1) * 16);
    const uint32_t bAddr = sbase + ATILE_B +
        (uint32_t)((wn * 64 + (quad >> 1) * 8 + li) * APITCH + (quad & 1) * 16);

#pragma unroll 4
    for (int i = 0; i < NIT; i++) {
        cp_wait<2>();
        __syncthreads();
        if (i + 3 < NIT)
            cp_stage(A, B, bm, bn, sbase + ((i + 3) & 3) * STAGE_B, tid, i + 3);
        cp_commit();

        const uint32_t sa = aAddr + (i & 3) * STAGE_B;
        const uint32_t sb = bAddr + (i & 3) * STAGE_B;
#pragma unroll
        for (int kh = 0; kh < 2; kh++) {
            uint32_t a[2][4];
            ldm_x4(a[0][0], a[0][1], a[0][2], a[0][3], sa + kh * 32);
            ldm_x4(a[1][0], a[1][1], a[1][2], a[1][3], sa + kh * 32 + 16 * APITCH);
            uint32_t b[8][2];
#pragma unroll
            for (int n2 = 0; n2 < 4; n2++)
                ldm_x4(b[2 * n2][0], b[2 * n2][1], b[2 * n2 + 1][0], b[2 * n2 + 1][1],
                       sb + kh * 32 + n2 * 16 * APITCH);
#pragma unroll
            for (int mb = 0; mb < 2; mb++)
#pragma unroll
                for (int nb = 0; nb < 8; nb++)
                    mma16816(acc[mb][nb], a[mb][0], a[mb][1], a[mb][2], a[mb][3],
                             b[nb][0], b[nb][1]);
        }
    }

    const int g = lane >> 2, t = lane & 3;
    float lsum[2][2] = {{0.f, 0.f}, {0.f, 0.f}};
#pragma unroll
    for (int mb = 0; mb < 2; mb++) {
        const int r0 = bm + wm * 32 + mb * 16 + g;
#pragma unroll
        for (int nb = 0; nb < 8; nb++) {
            const int col = bn + wn * 64 + nb * 8 + t * 2;
            const float b0 = bias[col], b1 = bias[col + 1];
            float v00 = acc[mb][nb][0] + b0, v01 = acc[mb][nb][1] + b1;
            float v10 = acc[mb][nb][2] + b0, v11 = acc[mb][nb][3] + b1;
            if (RELU) {
                v00 = fmaxf(v00, 0.f); v01 = fmaxf(v01, 0.f);
                v10 = fmaxf(v10, 0.f); v11 = fmaxf(v11, 0.f);
            }
            if (OUTS) {
                *(__half2*)(Cs + (size_t)r0 * N + col) =
                    __halves2half2(__float2half(v00), __float2half(v01));
                *(__half2*)(Cs + (size_t)(r0 + 8) * N + col) =
                    __halves2half2(__float2half(v10), __float2half(v11));
            }
            if (LOGITS) {
                const float w0 = w3[col], w1 = w3[col + 1];
                lsum[mb][0] = fmaf(v00, w0, fmaf(v01, w1, lsum[mb][0]));
                lsum[mb][1] = fmaf(v10, w0, fmaf(v11, w1, lsum[mb][1]));
            }
        }
    }
    if (LOGITS) {
#pragma unroll
        for (int mb = 0; mb < 2; mb++)
#pragma unroll
            for (int rr = 0; rr < 2; rr++) {
                float s = lsum[mb][rr];
                s += __shfl_xor_sync(0xffffffffu, s, 1);
                s += __shfl_xor_sync(0xffffffffu, s, 2);
                if (t == 0) {
                    int row = bm + wm * 32 + mb * 16 + g + rr * 8;
                    lpart[(size_t)row * 16 + bxLog * 2 + wn] = s;
                }
            }
    }
}

// DUAL 1: GEMM8 (gh3, 768 CTAs) + GEMM10-attr (256 CTAs)
__global__ void __launch_bounds__(256, 2)
gemm_dual(const float* __restrict__ b_hh, const float* __restrict__ b1)
{
    extern __shared__ char sm[];
    const uint32_t sbase = smem_u32(sm);
    const int tid = threadIdx.x, blk = blockIdx.x;
    if (blk < 768) {
        body128<false, true, false>(g2_h2rel, g2_Whh, b_hh, g2_gh3, H3,
                                    (blk / 24) * 128, (blk % 24) * 128,
                                    nullptr, nullptr, 0, sbase, tid);
    } else {
        int t = blk - 768;
        body128<true, true, false>(g2_clause, g2_W1, b1, g2_x1, H,
                                   NREL + (t >> 3) * 128, (t & 7) * 128,
                                   nullptr, nullptr, 0, sbase, tid);
    }
}

// DUAL 2: GEMM10-rel (256, drains first) + GEMM11-attr (logits, 256)
__global__ void __launch_bounds__(256, 2)
gemm_dual2(const float* __restrict__ b1, const float* __restrict__ b2,
           const float* __restrict__ w3, float* __restrict__ lpart)
{
    extern __shared__ char sm[];
    const uint32_t sbase = smem_u32(sm);
    const int tid = threadIdx.x, blk = blockIdx.x;
    if (blk < 256) {
        body128<true, true, false>(g2_clause, g2_W1, b1, g2_x1, H,
                                   (blk >> 3) * 128, (blk & 7) * 128,
                                   nullptr, nullptr, 0, sbase, tid);
    } else {
        int t = blk - 256;
        body128<true, false, true>(g2_x1, g2_W2, b2, nullptr, H,
                                   NREL + (t >> 3) * 128, (t & 7) * 128,
                                   w3, lpart, t & 7, sbase, tid);
    }
}

// GEMM11-rel (logits partials for rel rows, 256 CTAs)
__global__ void __launch_bounds__(256, 2)
gemm_logits_rel(const float* __restrict__ b2, const float* __restrict__ w3,
                float* __restrict__ lpart)
{
    extern __shared__ char sm[];
    body128<true, false, true>(g2_x1, g2_W2, b2, nullptr, H,
                               blockIdx.y * 128, blockIdx.x * 128,
                               w3, lpart, blockIdx.x, smem_u32(sm), threadIdx.x);
}

// ===================== 32x64 fp16 HMMA GEMM (small-M chain: GEMM1/2/4) ==========
// 8 warps: warp tile m16 x n16 (wm = w&1, wn = w>>1). 4-stage cp.async, 30KB smem.
#define ATILE32_B (32 * APITCH)              // 2560
#define STAGE32_B (ATILE32_B + 64 * APITCH)  // 7680
#define SMEM_DYN32 (4 * STAGE32_B)           // 30720 (<48KB, no opt-in)

__device__ __forceinline__ void cp_stage32(const __half* __restrict__ A,
                                           const __half* __restrict__ B,
                                           int bm, int bn, uint32_t sbase, int tid,
                                           int it)
{
    const int kk = it * 32;
    int row = tid >> 2, kc = tid & 3;
    cp16(sbase + ATILE32_B + row * APITCH + kc * 16,
         B + (size_t)(bn + row) * H + kk + kc * 8);
    if (tid < 128)
        cp16(sbase + row * APITCH + kc * 16,
             A + (size_t)(bm + row) * H + kk + kc * 8);
}

__device__ __forceinline__ void gemm32_body(
    const __half* __restrict__ A, const __half* __restrict__ B,
    const float* __restrict__ bias, __half* __restrict__ Cs, int N,
    int bm, int bn, uint32_t sbase, int tid)
{
    const int lane = tid & 31, w = tid >> 5;
    const int wm = w & 1, wn = w >> 1;       // m16 row group, n16 col group

#pragma unroll
    for (int s = 0; s < 3; s++) {
        cp_stage32(A, B, bm, bn, sbase + s * STAGE32_B, tid, s);
        cp_commit();
    }

    float acc[2][4];
#pragma unroll
    for (int nb = 0; nb < 2; nb++)
#pragma unroll
        for (int q = 0; q < 4; q++) acc[nb][q] = 0.f;

    const int quad = lane >> 3, li = lane & 7;
    const uint32_t aAddr = sbase +
        (uint32_t)((wm * 16 + (quad & 1) * 8 + li) * APITCH + (quad >> 1) * 16);
    const uint32_t bAddr = sbase + ATILE32_B +
        (uint32_t)((wn * 16 + (quad >> 1) * 8 + li) * APITCH + (quad & 1) * 16);

#pragma unroll 4
    for (int i = 0; i < NIT; i++) {
        cp_wait<2>();
        __syncthreads();
        if (i + 3 < NIT)
            cp_stage32(A, B, bm, bn, sbase + ((i + 3) & 3) * STAGE32_B, tid, i + 3);
        cp_commit();

        const uint32_t sa = aAddr + (i & 3) * STAGE32_B;
        const uint32_t sb = bAddr + (i & 3) * STAGE32_B;
#pragma unroll
        for (int kh = 0; kh < 2; kh++) {
            uint32_t a[4];
            ldm_x4(a[0], a[1], a[2], a[3], sa + kh * 32);
            uint32_t b[2][2];
            ldm_x4(b[0][0], b[0][1], b[1][0], b[1][1], sb + kh * 32);
            mma16816(acc[0], a[0], a[1], a[2], a[3], b[0][0], b[0][1]);
            mma16816(acc[1], a[0], a[1], a[2], a[3], b[1][0], b[1][1]);
        }
    }

    const int g = lane >> 2, t = lane & 3;
    const int r0 = bm + wm * 16 + g;
#pragma unroll
    for (int nb = 0; nb < 2; nb++) {
        const int col = bn + wn * 16 + nb * 8 + t * 2;
        const float b0 = bias[col], b1 = bias[col + 1];
        *(__half2*)(Cs + (size_t)r0 * N + col) = __halves2half2(
            __float2half(acc[nb][0] + b0), __float2half(acc[nb][1] + b1));
        *(__half2*)(Cs + (size_t)(r0 + 8) * N + col) = __halves2half2(
            __float2half(acc[nb][2] + b0), __float2half(acc[nb][3] + b1));
    }
}

// GEMM1 (128 CTAs) + convert W_hh (3072 rows) packed
__global__ void __launch_bounds__(256, 4)
gemm1_cvtWhh(const float* __restrict__ b_emb, const float* __restrict__ W_hh)
{
    extern __shared__ char sm[];
    const int blk = blockIdx.x, tid = threadIdx.x;
    if (blk < 128) {        // emb = table @ Wemb^T: 8 row-tiles x 16 col-tiles
        gemm32_body(g2_table, g2_Wemb, b_emb, g2_emb, H,
                    (blk >> 4) * 32, (blk & 15) * 64, smem_u32(sm), tid);
    } else {
        cvt_row(W_hh, g2_Whh, blk - 128, tid);
    }
}

// GEMM2 (384 CTAs) + convert W1, W2 (2048 rows) packed
__global__ void __launch_bounds__(256, 4)
gemm2_cvtW12(const float* __restrict__ b_ih,
             const float* __restrict__ W1, const float* __restrict__ W2)
{
    extern __shared__ char sm[];
    const int blk = blockIdx.x, tid = threadIdx.x;
    if (blk < 384) {        // gi = emb @ Wih^T: 8 row-tiles x 48 col-tiles
        gemm32_body(g2_emb, g2_Wih, b_ih, g2_gi, H3,
                    (blk / 48) * 32, (blk % 48) * 64, smem_u32(sm), tid);
    } else if (blk < 384 + 1024) {
        cvt_row(W1, g2_W1, blk - 384, tid);
    } else {
        cvt_row(W2, g2_W2, blk - 384 - 1024, tid);
    }
}

// GEMM4 (gh2, 384 CTAs)
__global__ void __launch_bounds__(256, 4)
gemm_gh2(const float* __restrict__ b_hh)
{
    extern __shared__ char sm[];
    gemm32_body(g2_h1, g2_Whh, b_hh, g2_gh2, H3,
                blockIdx.y * 32, blockIdx.x * 64, smem_u32(sm), threadIdx.x);
}

// ===================== launch 0: convert table/Wemb/Wih + gh1 GEMV =====================
#define CVT0_ROWS (256 + 1024 + 3072)   // 4352
__global__ void __launch_bounds__(256)
cvt_phase0(const float* __restrict__ table, const float* __restrict__ W_emb,
           const float* __restrict__ W_ih,
           const float* __restrict__ state, const float* __restrict__ W_hh,
           const float* __restrict__ b_hh)
{
    int row = blockIdx.x;
    int tid = threadIdx.x;
    if (row >= CVT0_ROWS) {          // gh1 GEMV: 384 blocks x 8 warps
        int n = (row - CVT0_ROWS) * 8 + (tid >> 5);
        int lane = tid & 31;
        const float* w = W_hh + (size_t)n * H;
        float s = 0.f;
#pragma unroll
        for (int k = lane * 4; k < H; k += 128) {
            float4 wv = *(const float4*)(w + k);
            float4 xv = *(const float4*)(state + k);
            s = fmaf(wv.x, xv.x, s); s = fmaf(wv.y, xv.y, s);
            s = fmaf(wv.z, xv.z, s); s = fmaf(wv.w, xv.w, s);
        }
#pragma unroll
        for (int o = 16; o; o >>= 1) s += __shfl_xor_sync(0xffffffffu, s, o);
        if (lane == 0) g_gh1[n] = s + b_hh[n];
        return;
    }
    int r = row;
    if      (r < 256)            cvt_row(table, g2_table, r, tid);
    else if ((r -= 256) < 1024)  cvt_row(W_emb, g2_Wemb, r, tid);
    else                          cvt_row(W_ih, g2_Wih, r - 1024, tid);
}

// ===================== GRU combine =====================
__device__ __forceinline__ float4 ld4h(const __half* p) {
    float2 f0 = __half22float2(*(const __half2*)p);
    float2 f1 = __half22float2(*(const __half2*)(p + 2));
    return make_float4(f0.x, f0.y, f1.x, f1.y);
}
__device__ __forceinline__ float gru1(float ir, float iz, float inn,
                                      float hr, float hz, float hn, float h)
{
    float r = 1.f / (1.f + __expf(-(ir + hr)));
    float z = 1.f / (1.f + __expf(-(iz + hz)));
    float n = tanh_fast(fmaf(r, hn, inn));
    return fmaf(z, h - n, n);
}
__device__ __forceinline__ float4 gru4_comb(float4 ir, float4 iz, float4 inn,
                                            float4 hr, float4 hz, float4 hn, float4 hv)
{
    float4 o;
    o.x = gru1(ir.x, iz.x, inn.x, hr.x, hz.x, hn.x, hv.x);
    o.y = gru1(ir.y, iz.y, inn.y, hr.y, hz.y, hn.y, hv.y);
    o.z = gru1(ir.z, iz.z, inn.z, hr.z, hz.z, hn.z, hv.z);
    o.w = gru1(ir.w, iz.w, inn.w, hr.w, hz.w, hn.w, hv.w);
    return o;
}
__device__ __forceinline__ void cvt_store(__half* o, float4 v)
{
    *(__half2*)(o)     = __halves2half2(__float2half(v.x), __float2half(v.y));
    *(__half2*)(o + 2) = __halves2half2(__float2half(v.z), __float2half(v.w));
}

// h1: 512 blocks, 2 elems/thread (2x block concurrency for latency hiding)
__global__ void gru_h1_kernel(const float* __restrict__ state)
{
    int v = blockIdx.x >> 1;
    int j = (blockIdx.x & 1) * 512 + threadIdx.x * 2;
    const __half* gi = g2_gi + (size_t)v * H3;
    float2 ir  = __half22float2(*(const __half2*)(gi + j));
    float2 iz  = __half22float2(*(const __half2*)(gi + H + j));
    float2 inn = __half22float2(*(const __half2*)(gi + 2 * H + j));
    float2 hr  = *(const float2*)(g_gh1 + j);
    float2 hz  = *(const float2*)(g_gh1 + H + j);
    float2 hn  = *(const float2*)(g_gh1 + 2 * H + j);
    float2 hv  = *(const float2*)(state + j);
    float o0 = gru1(ir.x, iz.x, inn.x, hr.x, hz.x, hn.x, hv.x);
    float o1 = gru1(ir.y, iz.y, inn.y, hr.y, hz.y, hn.y, hv.y);
    *(__half2*)(g2_h1 + (size_t)v * H + j) =
        __halves2half2(__float2half(o0), __float2half(o1));
}

__device__ __forceinline__ float4 gru4_hhh(const __half* gi, const __half* gh,
                                           const __half* h, int j)
{
    return gru4_comb(ld4h(gi + j), ld4h(gi + H + j), ld4h(gi + 2 * H + j),
                     ld4h(gh + j), ld4h(gh + H + j), ld4h(gh + 2 * H + j),
                     ld4h(h + j));
}

__global__ void gru_step2_all(const int* __restrict__ rel_tokens,
                              const int* __restrict__ attr_tokens)
{
    int blk = blockIdx.x;
    int j = threadIdx.x * 4;
    if (blk < NREL) {
        int t0 = rel_tokens[blk * 3 + 0];
        int t1 = rel_tokens[blk * 3 + 1];
        float4 o = gru4_hhh(g2_gi + (size_t)t1 * H3, g2_gh2 + (size_t)t0 * H3,
                            g2_h1 + (size_t)t0 * H, j);
        cvt_store(g2_h2rel + (size_t)blk * H + j, o);
    } else {
        int n = blk - NREL;
        int t0 = attr_tokens[n * 2 + 0];
        int t1 = attr_tokens[n * 2 + 1];
        float4 o = gru4_hhh(g2_gi + (size_t)t1 * H3, g2_gh2 + (size_t)t0 * H3,
                            g2_h1 + (size_t)t0 * H, j);
        cvt_store(g2_clause + (size_t)(NREL + n) * H + j, o);
    }
}

__global__ void gru_step3_kernel(const int* __restrict__ rel_tokens)
{
    int n  = blockIdx.x;
    int t2 = rel_tokens[n * 3 + 2];
    int j  = threadIdx.x * 4;
    float4 o = gru4_hhh(g2_gi + (size_t)t2 * H3, g2_gh3 + (size_t)n * H3,
                        g2_h2rel + (size_t)n * H, j);
    cvt_store(g2_clause + (size_t)n * H + j, o);
}

// ===================== logits reduce + softmax + eps smoothing =====================
__global__ void softmax_kernel(const float* __restrict__ eps, float* __restrict__ out)
{
    const int N = NCL;
    __shared__ float sl[NCL];
    __shared__ float shm[32], shs[32];
    int tid = threadIdx.x;

    for (int i = tid; i < N; i += 1024) {
        const float4* p = (const float4*)(g_lpart + (size_t)i * 16);
        float4 a = p[0], b = p[1], c = p[2], d = p[3];
        sl[i] = ((a.x + a.y) + (a.z + a.w)) + ((b.x + b.y) + (b.z + b.w))
              + ((c.x + c.y) + (c.z + c.w)) + ((d.x + d.y) + (d.z + d.w));
    }
    __syncthreads();

    float m = -1e30f;
    for (int i = tid; i < N; i += 1024) m = fmaxf(m, sl[i]);
#pragma unroll
    for (int o = 16; o; o >>= 1) m = fmaxf(m, __shfl_xor_sync(0xffffffffu, m, o));
    if ((tid & 31) == 0) shm[tid >> 5] = m;
    __syncthreads();
    if (tid < 32) {
        float v = shm[tid];
#pragma unroll
        for (int o = 16; o; o >>= 1) v = fmaxf(v, __shfl_xor_sync(0xffffffffu, v, o));
        shm[tid] = v;
    }
    __syncthreads();
    float M = shm[0];

    float s = 0.f;
    for (int i = tid; i < N; i += 1024) s += __expf(sl[i] - M);
#pragma unroll
    for (int o = 16; o; o >>= 1) s += __shfl_xor_sync(0xffffffffu, s, o);
    if ((tid & 31) == 0) shs[tid >> 5] = s;
    __syncthreads();
    if (tid < 32) {
        float v = shs[tid];
#pragma unroll
        for (int o = 16; o; o >>= 1) v += __shfl_xor_sync(0xffffffffu, v, o);
        shs[tid] = v;
    }
    __syncthreads();
    float S = shs[0];
    float e = eps[0];
    float inv = (1.f - e) / S;
    float add = e / (float)N;
    for (int i = tid; i < N; i += 1024)
        out[i] = __expf(sl[i] - M) * inv + add;
}

// ===================== launch =====================
extern "C" void kernel_launch(void* const* d_in, const int* in_sizes, int n_in,
                              void* d_out, int out_size)
{
    const float* state       = (const float*)d_in[0];
    const int*   rel_tokens  = (const int*)d_in[1];
    const int*   attr_tokens = (const int*)d_in[2];
    const float* table       = (const float*)d_in[3];
    const float* W_emb       = (const float*)d_in[4];
    const float* b_emb       = (const float*)d_in[5];
    const float* W_ih        = (const float*)d_in[6];
    const float* W_hh        = (const float*)d_in[7];
    const float* b_ih        = (const float*)d_in[8];
    const float* b_hh        = (const float*)d_in[9];
    const float* W1          = (const float*)d_in[10];
    const float* b1          = (const float*)d_in[11];
    const float* W2          = (const float*)d_in[12];
    const float* b2          = (const float*)d_in[13];
    const float* W3          = (const float*)d_in[14];
    const float* eps         = (const float*)d_in[16];
    float* out = (float*)d_out;

    float *p_lpart;
    cudaGetSymbolAddress((void**)&p_lpart, g_lpart);

    cudaFuncSetAttribute(gemm_dual,
                         cudaFuncAttributeMaxDynamicSharedMemorySize, SMEM_DYN_H);
    cudaFuncSetAttribute(gemm_dual2,
                         cudaFuncAttributeMaxDynamicSharedMemorySize, SMEM_DYN_H);
    cudaFuncSetAttribute(gemm_logits_rel,
                         cudaFuncAttributeMaxDynamicSharedMemorySize, SMEM_DYN_H);

    // 0. convert table/Wemb/Wih + gh1 GEMV
    cvt_phase0<<<CVT0_ROWS + 384, 256>>>(table, W_emb, W_ih, state, W_hh, b_hh);
    // 1. GEMM1 (emb, 128 CTAs of 32x64) + cvt W_hh (3072 rows)
    gemm1_cvtWhh<<<128 + 3072, 256, SMEM_DYN32>>>(b_emb, W_hh);
    // 2. GEMM2 (gi, 384 CTAs) + cvt W1/W2 (2048 rows)
    gemm2_cvtW12<<<384 + 2048, 256, SMEM_DYN32>>>(b_ih, W1, W2);
    // 3. h1_table (512 blocks, 2 elems/thread)
    gru_h1_kernel<<<2 * V, 256>>>(state);
    // 4. gh2_table (384 CTAs of 32x64)
    gemm_gh2<<<dim3(48, 8), 256, SMEM_DYN32>>>(b_hh);
    // 5. merged step-2 (rel + attr), all-fp16
    gru_step2_all<<<NREL + NATT, 256>>>(rel_tokens, attr_tokens);
    // 6. DUAL1: gh3 (768) + x1-attr (256)
    gemm_dual<<<1024, 256, SMEM_DYN_H>>>(b_hh, b1);
    // 7. rel step 3
    gru_step3_kernel<<<NREL, 256>>>(rel_tokens);
    // 8. DUAL2: x1-rel (256, drains first) + logits-attr (256)
    gemm_dual2<<<512, 256, SMEM_DYN_H>>>(b1, b2, W3, p_lpart);
    // 9. logits-rel (256)
    gemm_logits_rel<<<dim3(8, NREL / 128), 256, SMEM_DYN_H>>>(b2, W3, p_lpart);
    // 10. logits reduce + softmax + smoothing
    softmax_kernel<<<1, 1024>>>(eps, out);
}

// round 14
// speedup vs baseline: 1.0183x; 1.0183x over previous
#include <cuda_runtime.h>
#include <cuda_fp16.h>
#include <math.h>
#include <stdint.h>

#define H    1024
#define H3   3072
#define NREL 4096
#define NATT 4096
#define NCL  8192
#define V    256

// ===================== scratch (device globals; no allocations) =====================
__device__ __align__(256) __half g2_table[V * H];
__device__ __align__(256) __half g2_Wemb[H * H];
__device__ __align__(256) __half g2_Wih[H3 * H];
__device__ __align__(256) __half g2_Whh[H3 * H];
__device__ __align__(256) __half g2_W1[H * H];
__device__ __align__(256) __half g2_W2[H * H];
__device__ __align__(256) __half g2_emb[V * H];
__device__ __align__(256) __half g2_h1[V * H];
__device__ __align__(256) __half g2_h2rel[NREL * H];
__device__ __align__(256) __half g2_clause[NCL * H];
__device__ __align__(256) __half g2_x1[NCL * H];
__device__ __align__(256) __half g2_gi[V * H3];
__device__ __align__(256) __half g2_gh2[V * H3];
__device__ __align__(256) __half g2_gh3[NREL * H3];
__device__ float g_gh1[H3];
__device__ float g_lpart[NCL * 16];
__device__ int   g_cnt = 0;

// ===================== PTX helpers =====================
__device__ __forceinline__ uint32_t smem_u32(const void* p) {
    uint32_t a;
    asm("{ .reg .u64 t; cvta.to.shared.u64 t, %1; cvt.u32.u64 %0, t; }" : "=r"(a) : "l"(p));
    return a;
}
__device__ __forceinline__ void cp16(uint32_t dst, const void* src) {
    asm volatile("cp.async.cg.shared.global [%0], [%1], 16;" :: "r"(dst), "l"(src));
}
__device__ __forceinline__ void cp_commit() {
    asm volatile("cp.async.commit_group;" ::: "memory");
}
template <int N>
__device__ __forceinline__ void cp_wait() {
    asm volatile("cp.async.wait_group %0;" :: "n"(N) : "memory");
}
__device__ __forceinline__ void ldm_x4(uint32_t& r0, uint32_t& r1, uint32_t& r2, uint32_t& r3,
                                       uint32_t addr) {
    asm volatile("ldmatrix.sync.aligned.m8n8.x4.shared.b16 {%0,%1,%2,%3}, [%4];"
                 : "=r"(r0), "=r"(r1), "=r"(r2), "=r"(r3) : "r"(addr));
}
__device__ __forceinline__ void mma16816(float* c, uint32_t a0, uint32_t a1, uint32_t a2,
                                         uint32_t a3, uint32_t b0, uint32_t b1) {
    asm volatile(
        "mma.sync.aligned.m16n8k16.row.col.f32.f16.f16.f32 "
        "{%0,%1,%2,%3}, {%4,%5,%6,%7}, {%8,%9}, {%0,%1,%2,%3};"
        : "+f"(c[0]), "+f"(c[1]), "+f"(c[2]), "+f"(c[3])
        : "r"(a0), "r"(a1), "r"(a2), "r"(a3), "r"(b0), "r"(b1));
}
__device__ __forceinline__ float tanh_fast(float x) {
    float y;
    asm("tanh.approx.f32 %0, %1;" : "=f"(y) : "f"(x));
    return y;
}

// fp32 row -> fp16 row (256 threads, 4 elems each)
__device__ __forceinline__ void cvt_row(const float* __restrict__ src,
                                        __half* __restrict__ dst, int r, int tid)
{
    int c4 = tid * 4;
    float4 x = *(const float4*)(src + (size_t)r * H + c4);
    __half* o = dst + (size_t)r * H + c4;
    *(__half2*)(o)     = __halves2half2(__float2half(x.x), __float2half(x.y));
    *(__half2*)(o + 2) = __halves2half2(__float2half(x.z), __float2half(x.w));
}

#define APITCH   80
#define NIT      32

// ===================== shared 128x128 fp16 HMMA body ====================
#define ATILE_B  (128 * APITCH)
#define STAGE_B  (2 * ATILE_B)
#define SMEM_DYN_H (4 * STAGE_B)        // 81920

__device__ __forceinline__ void cp_stage(const __half* __restrict__ A,
                                         const __half* __restrict__ B,
                                         int bm, int bn, uint32_t sbase, int tid,
                                         int it)
{
    const int kk = it * 32;
#pragma unroll
    for (int h = 0; h < 2; h++) {
        int c = tid + h * 256;
        int row = c >> 2, kc = c & 3;
        cp16(sbase + row * APITCH + kc * 16,
             A + (size_t)(bm + row) * H + kk + kc * 8);
    }
#pragma unroll
    for (int h = 0; h < 2; h++) {
        int c = tid + h * 256;
        int row = c >> 2, kc = c & 3;
        cp16(sbase + ATILE_B + row * APITCH + kc * 16,
             B + (size_t)(bn + row) * H + kk + kc * 8);
    }
}

template <bool RELU, bool OUTS, bool LOGITS>
__device__ __forceinline__ void body128(
    const __half* __restrict__ A, const __half* __restrict__ B,
    const float* __restrict__ bias, __half* __restrict__ Cs, int N,
    int bm, int bn,
    const float* __restrict__ w3, float* __restrict__ lpart, int bxLog,
    uint32_t sbase, int tid)
{
    const int lane = tid & 31, w = tid >> 5;
    const int wm = w & 3, wn = w >> 2;

#pragma unroll
    for (int s = 0; s < 3; s++) {
        cp_stage(A, B, bm, bn, sbase + s * STAGE_B, tid, s);
        cp_commit();
    }

    float acc[2][8][4];
#pragma unroll
    for (int mb = 0; mb < 2; mb++)
#pragma unroll
        for (int nb = 0; nb < 8; nb++)
#pragma unroll
            for (int q = 0; q < 4; q++) acc[mb][nb][q] = 0.f;

    const int quad = lane >> 3, li = lane & 7;
    const uint32_t aAddr = sbase +
        (uint32_t)((wm * 32 + (quad & 1) * 8 + li) * APITCH + (quad >> 1) * 16);
    const uint32_t bAddr = sbase + ATILE_B +
        (uint32_t)((wn * 64 + (quad >> 1) * 8 + li) * APITCH + (quad & 1) * 16);

#pragma unroll 4
    for (int i = 0; i < NIT; i++) {
        cp_wait<2>();
        __syncthreads();
        if (i + 3 < NIT)
            cp_stage(A, B, bm, bn, sbase + ((i + 3) & 3) * STAGE_B, tid, i + 3);
        cp_commit();

        const uint32_t sa = aAddr + (i & 3) * STAGE_B;
        const uint32_t sb = bAddr + (i & 3) * STAGE_B;
#pragma unroll
        for (int kh = 0; kh < 2; kh++) {
            uint32_t a[2][4];
            ldm_x4(a[0][0], a[0][1], a[0][2], a[0][3], sa + kh * 32);
            ldm_x4(a[1][0], a[1][1], a[1][2], a[1][3], sa + kh * 32 + 16 * APITCH);
            uint32_t b[8][2];
#pragma unroll
            for (int n2 = 0; n2 < 4; n2++)
                ldm_x4(b[2 * n2][0], b[2 * n2][1], b[2 * n2 + 1][0], b[2 * n2 + 1][1],
                       sb + kh * 32 + n2 * 16 * APITCH);
#pragma unroll
            for (int mb = 0; mb < 2; mb++)
#pragma unroll
                for (int nb = 0; nb < 8; nb++)
                    mma16816(acc[mb][nb], a[mb][0], a[mb][1], a[mb][2], a[mb][3],
                             b[nb][0], b[nb][1]);
        }
    }

    const int g = lane >> 2, t = lane & 3;
    float lsum[2][2] = {{0.f, 0.f}, {0.f, 0.f}};
#pragma unroll
    for (int mb = 0; mb < 2; mb++) {
        const int r0 = bm + wm * 32 + mb * 16 + g;
#pragma unroll
        for (int nb = 0; nb < 8; nb++) {
            const int col = bn + wn * 64 + nb * 8 + t * 2;
            const float b0 = bias[col], b1 = bias[col + 1];
            float v00 = acc[mb][nb][0] + b0, v01 = acc[mb][nb][1] + b1;
            float v10 = acc[mb][nb][2] + b0, v11 = acc[mb][nb][3] + b1;
            if (RELU) {
                v00 = fmaxf(v00, 0.f); v01 = fmaxf(v01, 0.f);
                v10 = fmaxf(v10, 0.f); v11 = fmaxf(v11, 0.f);
            }
            if (OUTS) {
                *(__half2*)(Cs + (size_t)r0 * N + col) =
                    __halves2half2(__float2half(v00), __float2half(v01));
                *(__half2*)(Cs + (size_t)(r0 + 8) * N + col) =
                    __halves2half2(__float2half(v10), __float2half(v11));
            }
            if (LOGITS) {
                const float w0 = w3[col], w1 = w3[col + 1];
                lsum[mb][0] = fmaf(v00, w0, fmaf(v01, w1, lsum[mb][0]));
                lsum[mb][1] = fmaf(v10, w0, fmaf(v11, w1, lsum[mb][1]));
            }
        }
    }
    if (LOGITS) {
#pragma unroll
        for (int mb = 0; mb < 2; mb++)
#pragma unroll
            for (int rr = 0; rr < 2; rr++) {
                float s = lsum[mb][rr];
                s += __shfl_xor_sync(0xffffffffu, s, 1);
                s += __shfl_xor_sync(0xffffffffu, s, 2);
                if (t == 0) {
                    int row = bm + wm * 32 + mb * 16 + g + rr * 8;
                    lpart[(size_t)row * 16 + bxLog * 2 + wn] = s;
                }
            }
    }
}

// DUAL 1: GEMM8 (gh3, 768 CTAs) + GEMM10-attr (256 CTAs)
__global__ void __launch_bounds__(256, 2)
gemm_dual(const float* __restrict__ b_hh, const float* __restrict__ b1)
{
    extern __shared__ char sm[];
    const uint32_t sbase = smem_u32(sm);
    const int tid = threadIdx.x, blk = blockIdx.x;
    if (blk < 768) {
        body128<false, true, false>(g2_h2rel, g2_Whh, b_hh, g2_gh3, H3,
                                    (blk / 24) * 128, (blk % 24) * 128,
                                    nullptr, nullptr, 0, sbase, tid);
    } else {
        int t = blk - 768;
        body128<true, true, false>(g2_clause, g2_W1, b1, g2_x1, H,
                                   NREL + (t >> 3) * 128, (t & 7) * 128,
                                   nullptr, nullptr, 0, sbase, tid);
    }
}

// DUAL 2: GEMM10-rel (256, drains first) + GEMM11-attr (logits, 256)
__global__ void __launch_bounds__(256, 2)
gemm_dual2(const float* __restrict__ b1, const float* __restrict__ b2,
           const float* __restrict__ w3, float* __restrict__ lpart)
{
    extern __shared__ char sm[];
    const uint32_t sbase = smem_u32(sm);
    const int tid = threadIdx.x, blk = blockIdx.x;
    if (blk < 256) {
        body128<true, true, false>(g2_clause, g2_W1, b1, g2_x1, H,
                                   (blk >> 3) * 128, (blk & 7) * 128,
                                   nullptr, nullptr, 0, sbase, tid);
    } else {
        int t = blk - 256;
        body128<true, false, true>(g2_x1, g2_W2, b2, nullptr, H,
                                   NREL + (t >> 3) * 128, (t & 7) * 128,
                                   w3, lpart, t & 7, sbase, tid);
    }
}

// GEMM11-rel (logits partials, 256 CTAs) with fused final softmax
__global__ void __launch_bounds__(256, 2)
gemm_logits_rel(const float* __restrict__ b2, const float* __restrict__ w3,
                float* __restrict__ lpart,
                const float* __restrict__ eps, float* __restrict__ out)
{
    extern __shared__ char sm[];
    const int tid = threadIdx.x;
    body128<true, false, true>(g2_x1, g2_W2, b2, nullptr, H,
                               blockIdx.y * 128, blockIdx.x * 128,
                               w3, lpart, blockIdx.x, smem_u32(sm), tid);

    // last-CTA softmax (deterministic output; counter reset by cvt_phase0)
    __threadfence();
    __syncthreads();
    __shared__ int s_last;
    if (tid == 0) s_last = (atomicAdd(&g_cnt, 1) == 255) ? 1 : 0;
    __syncthreads();
    if (!s_last) return;

    float* sl = (float*)sm;          // reuse 80KB dynamic smem (32KB needed)
    __shared__ float shm[8], shs[8];
    for (int i = tid; i < NCL; i += 256) {
        const float4* p = (const float4*)(g_lpart + (size_t)i * 16);
        float4 a = p[0], b = p[1], c = p[2], d = p[3];
        sl[i] = ((a.x + a.y) + (a.z + a.w)) + ((b.x + b.y) + (b.z + b.w))
              + ((c.x + c.y) + (c.z + c.w)) + ((d.x + d.y) + (d.z + d.w));
    }
    __syncthreads();

    float m = -1e30f;
    for (int i = tid; i < NCL; i += 256) m = fmaxf(m, sl[i]);
#pragma unroll
    for (int o = 16; o; o >>= 1) m = fmaxf(m, __shfl_xor_sync(0xffffffffu, m, o));
    if ((tid & 31) == 0) shm[tid >> 5] = m;
    __syncthreads();
    if (tid < 8) {
        float v = shm[tid];
#pragma unroll
        for (int o = 4; o; o >>= 1) v = fmaxf(v, __shfl_xor_sync(0xffu, v, o));
        shm[tid] = v;
    }
    __syncthreads();
    float M = fmaxf(fmaxf(fmaxf(shm[0], shm[1]), fmaxf(shm[2], shm[3])),
                    fmaxf(fmaxf(shm[4], shm[5]), fmaxf(shm[6], shm[7])));

    float s = 0.f;
    for (int i = tid; i < NCL; i += 256) s += __expf(sl[i] - M);
#pragma unroll
    for (int o = 16; o; o >>= 1) s += __shfl_xor_sync(0xffffffffu, s, o);
    if ((tid & 31) == 0) shs[tid >> 5] = s;
    __syncthreads();
    float S = 0.f;
    if (tid == 0) {
#pragma unroll
        for (int i = 0; i < 8; i++) S += shs[i];
        shs[0] = S;
    }
    __syncthreads();
    S = shs[0];
    float e = eps[0];
    float inv = (1.f - e) / S;
    float add = e / (float)NCL;
    for (int i = tid; i < NCL; i += 256)
        out[i] = __expf(sl[i] - M) * inv + add;
}

// ===================== 64x64 fp16 HMMA GEMM (R12 config, reverted) ==============
#define ATILE64_B (64 * APITCH)
#define STAGE64_B (2 * ATILE64_B)
#define SMEM_DYN64 (4 * STAGE64_B)       // 40960

__device__ __forceinline__ void cp_stage64(const __half* __restrict__ A,
                                           const __half* __restrict__ B,
                                           int bm, int bn, uint32_t sbase, int tid,
                                           int it)
{
    const int kk = it * 32;
    int row = tid >> 2, kc = tid & 3;
    cp16(sbase + row * APITCH + kc * 16,
         A + (size_t)(bm + row) * H + kk + kc * 8);
    cp16(sbase + ATILE64_B + row * APITCH + kc * 16,
         B + (size_t)(bn + row) * H + kk + kc * 8);
}

__device__ __forceinline__ void gemm64_body(
    const __half* __restrict__ A, const __half* __restrict__ B,
    const float* __restrict__ bias, __half* __restrict__ Cs, int N,
    int bm, int bn, uint32_t sbase, int tid)
{
    const int lane = tid & 31, w = tid >> 5;
    const int wm = w & 1, wn = w >> 1;

#pragma unroll
    for (int s = 0; s < 3; s++) {
        cp_stage64(A, B, bm, bn, sbase + s * STAGE64_B, tid, s);
        cp_commit();
    }

    float acc[2][2][4];
#pragma unroll
    for (int mb = 0; mb < 2; mb++)
#pragma unroll
        for (int nb = 0; nb < 2; nb++)
#pragma unroll
            for (int q = 0; q < 4; q++) acc[mb][nb][q] = 0.f;

    const int quad = lane >> 3, li = lane & 7;
    const uint32_t aAddr = sbase +
        (uint32_t)((wm * 32 + (quad & 1) * 8 + li) * APITCH + (quad >> 1) * 16);
    const uint32_t bAddr = sbase + ATILE64_B +
        (uint32_t)((wn * 16 + (quad >> 1) * 8 + li) * APITCH + (quad & 1) * 16);

#pragma unroll 4
    for (int i = 0; i < NIT; i++) {
        cp_wait<2>();
        __syncthreads();
        if (i + 3 < NIT)
            cp_stage64(A, B, bm, bn, sbase + ((i + 3) & 3) * STAGE64_B, tid, i + 3);
        cp_commit();

        const uint32_t sa = aAddr + (i & 3) * STAGE64_B;
        const uint32_t sb = bAddr + (i & 3) * STAGE64_B;
#pragma unroll
        for (int kh = 0; kh < 2; kh++) {
            uint32_t a[2][4];
            ldm_x4(a[0][0], a[0][1], a[0][2], a[0][3], sa + kh * 32);
            ldm_x4(a[1][0], a[1][1], a[1][2], a[1][3], sa + kh * 32 + 16 * APITCH);
            uint32_t b[2][2];
            ldm_x4(b[0][0], b[0][1], b[1][0], b[1][1], sb + kh * 32);
#pragma unroll
            for (int mb = 0; mb < 2; mb++)
#pragma unroll
                for (int nb = 0; nb < 2; nb++)
                    mma16816(acc[mb][nb], a[mb][0], a[mb][1], a[mb][2], a[mb][3],
                             b[nb][0], b[nb][1]);
        }
    }

    const int g = lane >> 2, t = lane & 3;
#pragma unroll
    for (int mb = 0; mb < 2; mb++) {
        const int r0 = bm + wm * 32 + mb * 16 + g;
#pragma unroll
        for (int nb = 0; nb < 2; nb++) {
            const int col = bn + wn * 16 + nb * 8 + t * 2;
            const float b0 = bias[col], b1 = bias[col + 1];
            *(__half2*)(Cs + (size_t)r0 * N + col) = __halves2half2(
                __float2half(acc[mb][nb][0] + b0), __float2half(acc[mb][nb][1] + b1));
            *(__half2*)(Cs + (size_t)(r0 + 8) * N + col) = __halves2half2(
                __float2half(acc[mb][nb][2] + b0), __float2half(acc[mb][nb][3] + b1));
        }
    }
}

// GEMM1 (64 CTAs) + convert W_hh (3072 rows)
__global__ void __launch_bounds__(256, 2)
gemm1_cvtWhh(const float* __restrict__ b_emb, const float* __restrict__ W_hh)
{
    extern __shared__ char sm[];
    const int blk = blockIdx.x, tid = threadIdx.x;
    if (blk < 64) {
        gemm64_body(g2_table, g2_Wemb, b_emb, g2_emb, H,
                    (blk >> 4) * 64, (blk & 15) * 64, smem_u32(sm), tid);
    } else {
        cvt_row(W_hh, g2_Whh, blk - 64, tid);
    }
}

// GEMM2 (192 CTAs) + convert W1, W2 (2048 rows)
__global__ void __launch_bounds__(256, 2)
gemm2_cvtW12(const float* __restrict__ b_ih,
             const float* __restrict__ W1, const float* __restrict__ W2)
{
    extern __shared__ char sm[];
    const int blk = blockIdx.x, tid = threadIdx.x;
    if (blk < 192) {
        gemm64_body(g2_emb, g2_Wih, b_ih, g2_gi, H3,
                    (blk / 48) * 64, (blk % 48) * 64, smem_u32(sm), tid);
    } else if (blk < 192 + 1024) {
        cvt_row(W1, g2_W1, blk - 192, tid);
    } else {
        cvt_row(W2, g2_W2, blk - 192 - 1024, tid);
    }
}

// GEMM4 (gh2, 192 CTAs)
__global__ void __launch_bounds__(256, 2)
gemm_hmma64(const __half* __restrict__ A, const __half* __restrict__ B,
            const float* __restrict__ bias, __half* __restrict__ Cs, int N)
{
    extern __shared__ char sm[];
    gemm64_body(A, B, bias, Cs, N,
                blockIdx.y * 64, blockIdx.x * 64, smem_u32(sm), threadIdx.x);
}

// ===================== launch 0: convert table/Wemb/Wih + gh1 GEMV + cnt reset =====================
#define CVT0_ROWS (256 + 1024 + 3072)   // 4352
__global__ void __launch_bounds__(256)
cvt_phase0(const float* __restrict__ table, const float* __restrict__ W_emb,
           const float* __restrict__ W_ih,
           const float* __restrict__ state, const float* __restrict__ W_hh,
           const float* __restrict__ b_hh)
{
    int row = blockIdx.x;
    int tid = threadIdx.x;
    if (row == 0 && tid == 0) g_cnt = 0;
    if (row >= CVT0_ROWS) {          // gh1 GEMV: 384 blocks x 8 warps
        int n = (row - CVT0_ROWS) * 8 + (tid >> 5);
        int lane = tid & 31;
        const float* w = W_hh + (size_t)n * H;
        float s = 0.f;
#pragma unroll
        for (int k = lane * 4; k < H; k += 128) {
            float4 wv = *(const float4*)(w + k);
            float4 xv = *(const float4*)(state + k);
            s = fmaf(wv.x, xv.x, s); s = fmaf(wv.y, xv.y, s);
            s = fmaf(wv.z, xv.z, s); s = fmaf(wv.w, xv.w, s);
        }
#pragma unroll
        for (int o = 16; o; o >>= 1) s += __shfl_xor_sync(0xffffffffu, s, o);
        if (lane == 0) g_gh1[n] = s + b_hh[n];
        return;
    }
    int r = row;
    if      (r < 256)            cvt_row(table, g2_table, r, tid);
    else if ((r -= 256) < 1024)  cvt_row(W_emb, g2_Wemb, r, tid);
    else                          cvt_row(W_ih, g2_Wih, r - 1024, tid);
}

// ===================== GRU combine =====================
__device__ __forceinline__ float4 ld4h(const __half* p) {
    float2 f0 = __half22float2(*(const __half2*)p);
    float2 f1 = __half22float2(*(const __half2*)(p + 2));
    return make_float4(f0.x, f0.y, f1.x, f1.y);
}
__device__ __forceinline__ float gru1(float ir, float iz, float inn,
                                      float hr, float hz, float hn, float h)
{
    float r = 1.f / (1.f + __expf(-(ir + hr)));
    float z = 1.f / (1.f + __expf(-(iz + hz)));
    float n = tanh_fast(fmaf(r, hn, inn));
    return fmaf(z, h - n, n);
}
__device__ __forceinline__ float4 gru4_comb(float4 ir, float4 iz, float4 inn,
                                            float4 hr, float4 hz, float4 hn, float4 hv)
{
    float4 o;
    o.x = gru1(ir.x, iz.x, inn.x, hr.x, hz.x, hn.x, hv.x);
    o.y = gru1(ir.y, iz.y, inn.y, hr.y, hz.y, hn.y, hv.y);
    o.z = gru1(ir.z, iz.z, inn.z, hr.z, hz.z, hn.z, hv.z);
    o.w = gru1(ir.w, iz.w, inn.w, hr.w, hz.w, hn.w, hv.w);
    return o;
}
__device__ __forceinline__ void cvt_store(__half* o, float4 v)
{
    *(__half2*)(o)     = __halves2half2(__float2half(v.x), __float2half(v.y));
    *(__half2*)(o + 2) = __halves2half2(__float2half(v.z), __float2half(v.w));
}

// h1: 512 blocks, 2 elems/thread (R13's one win — kept)
__global__ void gru_h1_kernel(const float* __restrict__ state)
{
    int v = blockIdx.x >> 1;
    int j = (blockIdx.x & 1) * 512 + threadIdx.x * 2;
    const __half* gi = g2_gi + (size_t)v * H3;
    float2 ir  = __half22float2(*(const __half2*)(gi + j));
    float2 iz  = __half22float2(*(const __half2*)(gi + H + j));
    float2 inn = __half22float2(*(const __half2*)(gi + 2 * H + j));
    float2 hr  = *(const float2*)(g_gh1 + j);
    float2 hz  = *(const float2*)(g_gh1 + H + j);
    float2 hn  = *(const float2*)(g_gh1 + 2 * H + j);
    float2 hv  = *(const float2*)(state + j);
    float o0 = gru1(ir.x, iz.x, inn.x, hr.x, hz.x, hn.x, hv.x);
    float o1 = gru1(ir.y, iz.y, inn.y, hr.y, hz.y, hn.y, hv.y);
    *(__half2*)(g2_h1 + (size_t)v * H + j) =
        __halves2half2(__float2half(o0), __float2half(o1));
}

__device__ __forceinline__ float4 gru4_hhh(const __half* gi, const __half* gh,
                                           const __half* h, int j)
{
    return gru4_comb(ld4h(gi + j), ld4h(gi + H + j), ld4h(gi + 2 * H + j),
                     ld4h(gh + j), ld4h(gh + H + j), ld4h(gh + 2 * H + j),
                     ld4h(h + j));
}

__global__ void gru_step2_all(const int* __restrict__ rel_tokens,
                              const int* __restrict__ attr_tokens)
{
    int blk = blockIdx.x;
    int j = threadIdx.x * 4;
    if (blk < NREL) {
        int t0 = rel_tokens[blk * 3 + 0];
        int t1 = rel_tokens[blk * 3 + 1];
        float4 o = gru4_hhh(g2_gi + (size_t)t1 * H3, g2_gh2 + (size_t)t0 * H3,
                            g2_h1 + (size_t)t0 * H, j);
        cvt_store(g2_h2rel + (size_t)blk * H + j, o);
    } else {
        int n = blk - NREL;
        int t0 = attr_tokens[n * 2 + 0];
        int t1 = attr_tokens[n * 2 + 1];
        float4 o = gru4_hhh(g2_gi + (size_t)t1 * H3, g2_gh2 + (size_t)t0 * H3,
                            g2_h1 + (size_t)t0 * H, j);
        cvt_store(g2_clause + (size_t)(NREL + n) * H + j, o);
    }
}

__global__ void gru_step3_kernel(const int* __restrict__ rel_tokens)
{
    int n  = blockIdx.x;
    int t2 = rel_tokens[n * 3 + 2];
    int j  = threadIdx.x * 4;
    float4 o = gru4_hhh(g2_gi + (size_t)t2 * H3, g2_gh3 + (size_t)n * H3,
                        g2_h2rel + (size_t)n * H, j);
    cvt_store(g2_clause + (size_t)n * H + j, o);
}

// ===================== launch =====================
extern "C" void kernel_launch(void* const* d_in, const int* in_sizes, int n_in,
                              void* d_out, int out_size)
{
    const float* state       = (const float*)d_in[0];
    const int*   rel_tokens  = (const int*)d_in[1];
    const int*   attr_tokens = (const int*)d_in[2];
    const float* table       = (const float*)d_in[3];
    const float* W_emb       = (const float*)d_in[4];
    const float* b_emb       = (const float*)d_in[5];
    const float* W_ih        = (const float*)d_in[6];
    const float* W_hh        = (const float*)d_in[7];
    const float* b_ih        = (const float*)d_in[8];
    const float* b_hh        = (const float*)d_in[9];
    const float* W1          = (const float*)d_in[10];
    const float* b1          = (const float*)d_in[11];
    const float* W2          = (const float*)d_in[12];
    const float* b2          = (const float*)d_in[13];
    const float* W3          = (const float*)d_in[14];
    const float* eps         = (const float*)d_in[16];
    float* out = (float*)d_out;

    __half *p2_h1, *p2_Whh, *p2_gh2;
    float *p_lpart;
    cudaGetSymbolAddress((void**)&p2_h1,   g2_h1);
    cudaGetSymbolAddress((void**)&p2_Whh,  g2_Whh);
    cudaGetSymbolAddress((void**)&p2_gh2,  g2_gh2);
    cudaGetSymbolAddress((void**)&p_lpart, g_lpart);

    cudaFuncSetAttribute(gemm_dual,
                         cudaFuncAttributeMaxDynamicSharedMemorySize, SMEM_DYN_H);
    cudaFuncSetAttribute(gemm_dual2,
                         cudaFuncAttributeMaxDynamicSharedMemorySize, SMEM_DYN_H);
    cudaFuncSetAttribute(gemm_logits_rel,
                         cudaFuncAttributeMaxDynamicSharedMemorySize, SMEM_DYN_H);

    // 0. convert table/Wemb/Wih + gh1 GEMV + counter reset
    cvt_phase0<<<CVT0_ROWS + 384, 256>>>(table, W_emb, W_ih, state, W_hh, b_hh);
    // 1. GEMM1 (emb, 64 CTAs of 64x64) + cvt W_hh
    gemm1_cvtWhh<<<64 + 3072, 256, SMEM_DYN64>>>(b_emb, W_hh);
    // 2. GEMM2 (gi, 192 CTAs) + cvt W1/W2
    gemm2_cvtW12<<<192 + 2048, 256, SMEM_DYN64>>>(b_ih, W1, W2);
    // 3. h1_table (512 blocks)
    gru_h1_kernel<<<2 * V, 256>>>(state);
    // 4. gh2_table (192 CTAs of 64x64)
    gemm_hmma64<<<dim3(H3 / 64, V / 64), 256, SMEM_DYN64>>>(
        p2_h1, p2_Whh, b_hh, p2_gh2, H3);
    // 5. merged step-2 (rel + attr)
    gru_step2_all<<<NREL + NATT, 256>>>(rel_tokens, attr_tokens);
    // 6. DUAL1: gh3 (768) + x1-attr (256)
    gemm_dual<<<1024, 256, SMEM_DYN_H>>>(b_hh, b1);
    // 7. rel step 3
    gru_step3_kernel<<<NREL, 256>>>(rel_tokens);
    // 8. DUAL2: x1-rel (256, drains first) + logits-attr (256)
    gemm_dual2<<<512, 256, SMEM_DYN_H>>>(b1, b2, W3, p_lpart);
    // 9. logits-rel (256) with fused last-CTA softmax + eps smoothing
    gemm_logits_rel<<<dim3(8, NREL / 128), 256, SMEM_DYN_H>>>(
        b2, W3, p_lpart, eps, out);
}

// round 15
// speedup vs baseline: 1.0457x; 1.0268x over previous
#include <cuda_runtime.h>
#include <cuda_fp16.h>
#include <math.h>
#include <stdint.h>

#define H    1024
#define H3   3072
#define NREL 4096
#define NATT 4096
#define NCL  8192
#define V    256

// ===================== scratch (device globals; no allocations) =====================
__device__ __align__(256) __half g2_table[V * H];
__device__ __align__(256) __half g2_Wemb[H * H];
__device__ __align__(256) __half g2_Wih[H3 * H];
__device__ __align__(256) __half g2_Whh[H3 * H];
__device__ __align__(256) __half g2_W1[H * H];
__device__ __align__(256) __half g2_W2[H * H];
__device__ __align__(256) __half g2_emb[V * H];
__device__ __align__(256) __half g2_h1[V * H];
__device__ __align__(256) __half g2_h2rel[NREL * H];
__device__ __align__(256) __half g2_clause[NCL * H];
__device__ __align__(256) __half g2_x1[NCL * H];
__device__ __align__(256) __half g2_gi[V * H3];
__device__ __align__(256) __half g2_gh2[V * H3];
__device__ __align__(256) __half g2_gh3[NREL * H3];
__device__ float g_gh1[H3];
__device__ float g_lpart[NCL * 16];
__device__ int   g_cnt = 0;

// ===================== PTX helpers =====================
__device__ __forceinline__ uint32_t smem_u32(const void* p) {
    uint32_t a;
    asm("{ .reg .u64 t; cvta.to.shared.u64 t, %1; cvt.u32.u64 %0, t; }" : "=r"(a) : "l"(p));
    return a;
}
__device__ __forceinline__ void cp16(uint32_t dst, const void* src) {
    asm volatile("cp.async.cg.shared.global [%0], [%1], 16;" :: "r"(dst), "l"(src));
}
__device__ __forceinline__ void cp_commit() {
    asm volatile("cp.async.commit_group;" ::: "memory");
}
template <int N>
__device__ __forceinline__ void cp_wait() {
    asm volatile("cp.async.wait_group %0;" :: "n"(N) : "memory");
}
__device__ __forceinline__ void ldm_x4(uint32_t& r0, uint32_t& r1, uint32_t& r2, uint32_t& r3,
                                       uint32_t addr) {
    asm volatile("ldmatrix.sync.aligned.m8n8.x4.shared.b16 {%0,%1,%2,%3}, [%4];"
                 : "=r"(r0), "=r"(r1), "=r"(r2), "=r"(r3) : "r"(addr));
}
__device__ __forceinline__ void mma16816(float* c, uint32_t a0, uint32_t a1, uint32_t a2,
                                         uint32_t a3, uint32_t b0, uint32_t b1) {
    asm volatile(
        "mma.sync.aligned.m16n8k16.row.col.f32.f16.f16.f32 "
        "{%0,%1,%2,%3}, {%4,%5,%6,%7}, {%8,%9}, {%0,%1,%2,%3};"
        : "+f"(c[0]), "+f"(c[1]), "+f"(c[2]), "+f"(c[3])
        : "r"(a0), "r"(a1), "r"(a2), "r"(a3), "r"(b0), "r"(b1));
}
__device__ __forceinline__ float tanh_fast(float x) {
    float y;
    asm("tanh.approx.f32 %0, %1;" : "=f"(y) : "f"(x));
    return y;
}

// fp32 row -> fp16 row (256 threads, 4 elems each)
__device__ __forceinline__ void cvt_row(const float* __restrict__ src,
                                        __half* __restrict__ dst, int r, int tid)
{
    int c4 = tid * 4;
    float4 x = *(const float4*)(src + (size_t)r * H + c4);
    __half* o = dst + (size_t)r * H + c4;
    *(__half2*)(o)     = __halves2half2(__float2half(x.x), __float2half(x.y));
    *(__half2*)(o + 2) = __halves2half2(__float2half(x.z), __float2half(x.w));
}

// ===================== 128x128 BK=64 2-stage HMMA body (big GEMMs) ====================
#define KPITCH   144                    // 128B data + 16B pad; conflict-free ldmatrix
#define ATILE_K  (128 * KPITCH)         // 18432
#define STAGE_K  (2 * ATILE_K)          // 36864 (A then B)
#define SMEM_DYN_H (2 * STAGE_K)        // 73728
#define NIT_K    16                     // 16 chunks of K=64

__device__ __forceinline__ void cp_stageK(const __half* __restrict__ A,
                                          const __half* __restrict__ B,
                                          int bm, int bn, uint32_t sbase, int tid,
                                          int it)
{
    const int kk = it * 64;
#pragma unroll
    for (int h = 0; h < 4; h++) {
        int c = tid + h * 256;          // 1024 chunks of 16B for A
        int row = c >> 3, kc = c & 7;
        cp16(sbase + row * KPITCH + kc * 16,
             A + (size_t)(bm + row) * H + kk + kc * 8);
    }
#pragma unroll
    for (int h = 0; h < 4; h++) {
        int c = tid + h * 256;
        int row = c >> 3, kc = c & 7;
        cp16(sbase + ATILE_K + row * KPITCH + kc * 16,
             B + (size_t)(bn + row) * H + kk + kc * 8);
    }
}

template <bool RELU, bool OUTS, bool LOGITS>
__device__ __forceinline__ void body128(
    const __half* __restrict__ A, const __half* __restrict__ B,
    const float* __restrict__ bias, __half* __restrict__ Cs, int N,
    int bm, int bn,
    const float* __restrict__ w3, float* __restrict__ lpart, int bxLog,
    uint32_t sbase, int tid)
{
    const int lane = tid & 31, w = tid >> 5;
    const int wm = w & 3, wn = w >> 2;

    cp_stageK(A, B, bm, bn, sbase, tid, 0);
    cp_commit();

    float acc[2][8][4];
#pragma unroll
    for (int mb = 0; mb < 2; mb++)
#pragma unroll
        for (int nb = 0; nb < 8; nb++)
#pragma unroll
            for (int q = 0; q < 4; q++) acc[mb][nb][q] = 0.f;

    const int quad = lane >> 3, li = lane & 7;
    const uint32_t aAddr = sbase +
        (uint32_t)((wm * 32 + (quad & 1) * 8 + li) * KPITCH + (quad >> 1) * 16);
    const uint32_t bAddr = sbase + ATILE_K +
        (uint32_t)((wn * 64 + (quad >> 1) * 8 + li) * KPITCH + (quad & 1) * 16);

#pragma unroll 2
    for (int i = 0; i < NIT_K; i++) {
        cp_wait<0>();                // stage i resident
        __syncthreads();             // all warps done with the buffer being refilled
        if (i + 1 < NIT_K)
            cp_stageK(A, B, bm, bn, sbase + ((i + 1) & 1) * STAGE_K, tid, i + 1);
        cp_commit();

        const uint32_t sa = aAddr + (i & 1) * STAGE_K;
        const uint32_t sb = bAddr + (i & 1) * STAGE_K;
#pragma unroll
        for (int kh = 0; kh < 4; kh++) {
            uint32_t a[2][4];
            ldm_x4(a[0][0], a[0][1], a[0][2], a[0][3], sa + kh * 32);
            ldm_x4(a[1][0], a[1][1], a[1][2], a[1][3], sa + kh * 32 + 16 * KPITCH);
            uint32_t b[8][2];
#pragma unroll
            for (int n2 = 0; n2 < 4; n2++)
                ldm_x4(b[2 * n2][0], b[2 * n2][1], b[2 * n2 + 1][0], b[2 * n2 + 1][1],
                       sb + kh * 32 + n2 * 16 * KPITCH);
#pragma unroll
            for (int mb = 0; mb < 2; mb++)
#pragma unroll
                for (int nb = 0; nb < 8; nb++)
                    mma16816(acc[mb][nb], a[mb][0], a[mb][1], a[mb][2], a[mb][3],
                             b[nb][0], b[nb][1]);
        }
    }

    const int g = lane >> 2, t = lane & 3;
    float lsum[2][2] = {{0.f, 0.f}, {0.f, 0.f}};
#pragma unroll
    for (int mb = 0; mb < 2; mb++) {
        const int r0 = bm + wm * 32 + mb * 16 + g;
#pragma unroll
        for (int nb = 0; nb < 8; nb++) {
            const int col = bn + wn * 64 + nb * 8 + t * 2;
            const float b0 = bias[col], b1 = bias[col + 1];
            float v00 = acc[mb][nb][0] + b0, v01 = acc[mb][nb][1] + b1;
            float v10 = acc[mb][nb][2] + b0, v11 = acc[mb][nb][3] + b1;
            if (RELU) {
                v00 = fmaxf(v00, 0.f); v01 = fmaxf(v01, 0.f);
                v10 = fmaxf(v10, 0.f); v11 = fmaxf(v11, 0.f);
            }
            if (OUTS) {
                *(__half2*)(Cs + (size_t)r0 * N + col) =
                    __halves2half2(__float2half(v00), __float2half(v01));
                *(__half2*)(Cs + (size_t)(r0 + 8) * N + col) =
                    __halves2half2(__float2half(v10), __float2half(v11));
            }
            if (LOGITS) {
                const float w0 = w3[col], w1 = w3[col + 1];
                lsum[mb][0] = fmaf(v00, w0, fmaf(v01, w1, lsum[mb][0]));
                lsum[mb][1] = fmaf(v10, w0, fmaf(v11, w1, lsum[mb][1]));
            }
        }
    }
    if (LOGITS) {
#pragma unroll
        for (int mb = 0; mb < 2; mb++)
#pragma unroll
            for (int rr = 0; rr < 2; rr++) {
                float s = lsum[mb][rr];
                s += __shfl_xor_sync(0xffffffffu, s, 1);
                s += __shfl_xor_sync(0xffffffffu, s, 2);
                if (t == 0) {
                    int row = bm + wm * 32 + mb * 16 + g + rr * 8;
                    lpart[(size_t)row * 16 + bxLog * 2 + wn] = s;
                }
            }
    }
}

// DUAL 1: GEMM8 (gh3, 768 CTAs) + GEMM10-attr (256 CTAs)
__global__ void __launch_bounds__(256, 2)
gemm_dual(const float* __restrict__ b_hh, const float* __restrict__ b1)
{
    extern __shared__ char sm[];
    const uint32_t sbase = smem_u32(sm);
    const int tid = threadIdx.x, blk = blockIdx.x;
    if (blk < 768) {
        body128<false, true, false>(g2_h2rel, g2_Whh, b_hh, g2_gh3, H3,
                                    (blk / 24) * 128, (blk % 24) * 128,
                                    nullptr, nullptr, 0, sbase, tid);
    } else {
        int t = blk - 768;
        body128<true, true, false>(g2_clause, g2_W1, b1, g2_x1, H,
                                   NREL + (t >> 3) * 128, (t & 7) * 128,
                                   nullptr, nullptr, 0, sbase, tid);
    }
}

// DUAL 2: GEMM10-rel (256, drains first) + GEMM11-attr (logits, 256)
__global__ void __launch_bounds__(256, 2)
gemm_dual2(const float* __restrict__ b1, const float* __restrict__ b2,
           const float* __restrict__ w3, float* __restrict__ lpart)
{
    extern __shared__ char sm[];
    const uint32_t sbase = smem_u32(sm);
    const int tid = threadIdx.x, blk = blockIdx.x;
    if (blk < 256) {
        body128<true, true, false>(g2_clause, g2_W1, b1, g2_x1, H,
                                   (blk >> 3) * 128, (blk & 7) * 128,
                                   nullptr, nullptr, 0, sbase, tid);
    } else {
        int t = blk - 256;
        body128<true, false, true>(g2_x1, g2_W2, b2, nullptr, H,
                                   NREL + (t >> 3) * 128, (t & 7) * 128,
                                   w3, lpart, t & 7, sbase, tid);
    }
}

// GEMM11-rel (logits partials, 256 CTAs) with fused final softmax
__global__ void __launch_bounds__(256, 2)
gemm_logits_rel(const float* __restrict__ b2, const float* __restrict__ w3,
                float* __restrict__ lpart,
                const float* __restrict__ eps, float* __restrict__ out)
{
    extern __shared__ char sm[];
    const int tid = threadIdx.x;
    body128<true, false, true>(g2_x1, g2_W2, b2, nullptr, H,
                               blockIdx.y * 128, blockIdx.x * 128,
                               w3, lpart, blockIdx.x, smem_u32(sm), tid);

    // last-CTA softmax (deterministic output; counter reset by cvt_phase0)
    __threadfence();
    __syncthreads();
    __shared__ int s_last;
    if (tid == 0) s_last = (atomicAdd(&g_cnt, 1) == 255) ? 1 : 0;
    __syncthreads();
    if (!s_last) return;

    float* sl = (float*)sm;          // reuse 72KB dynamic smem (32KB needed)
    __shared__ float shm[8], shs[8];
    for (int i = tid; i < NCL; i += 256) {
        const float4* p = (const float4*)(g_lpart + (size_t)i * 16);
        float4 a = p[0], b = p[1], c = p[2], d = p[3];
        sl[i] = ((a.x + a.y) + (a.z + a.w)) + ((b.x + b.y) + (b.z + b.w))
              + ((c.x + c.y) + (c.z + c.w)) + ((d.x + d.y) + (d.z + d.w));
    }
    __syncthreads();

    float m = -1e30f;
    for (int i = tid; i < NCL; i += 256) m = fmaxf(m, sl[i]);
#pragma unroll
    for (int o = 16; o; o >>= 1) m = fmaxf(m, __shfl_xor_sync(0xffffffffu, m, o));
    if ((tid & 31) == 0) shm[tid >> 5] = m;
    __syncthreads();
    float M = fmaxf(fmaxf(fmaxf(shm[0], shm[1]), fmaxf(shm[2], shm[3])),
                    fmaxf(fmaxf(shm[4], shm[5]), fmaxf(shm[6], shm[7])));

    float s = 0.f;
    for (int i = tid; i < NCL; i += 256) s += __expf(sl[i] - M);
#pragma unroll
    for (int o = 16; o; o >>= 1) s += __shfl_xor_sync(0xffffffffu, s, o);
    if ((tid & 31) == 0) shs[tid >> 5] = s;
    __syncthreads();
    float S = 0.f;
    if (tid == 0) {
#pragma unroll
        for (int i = 0; i < 8; i++) S += shs[i];
        shs[0] = S;
    }
    __syncthreads();
    S = shs[0];
    float e = eps[0];
    float inv = (1.f - e) / S;
    float add = e / (float)NCL;
    for (int i = tid; i < NCL; i += 256)
        out[i] = __expf(sl[i] - M) * inv + add;
}

// ===================== 64x64 fp16 HMMA GEMM (small chain, unchanged) ==============
#define APITCH   80
#define NIT      32
#define ATILE64_B (64 * APITCH)
#define STAGE64_B (2 * ATILE64_B)
#define SMEM_DYN64 (4 * STAGE64_B)       // 40960

__device__ __forceinline__ void cp_stage64(const __half* __restrict__ A,
                                           const __half* __restrict__ B,
                                           int bm, int bn, uint32_t sbase, int tid,
                                           int it)
{
    const int kk = it * 32;
    int row = tid >> 2, kc = tid & 3;
    cp16(sbase + row * APITCH + kc * 16,
         A + (size_t)(bm + row) * H + kk + kc * 8);
    cp16(sbase + ATILE64_B + row * APITCH + kc * 16,
         B + (size_t)(bn + row) * H + kk + kc * 8);
}

__device__ __forceinline__ void gemm64_body(
    const __half* __restrict__ A, const __half* __restrict__ B,
    const float* __restrict__ bias, __half* __restrict__ Cs, int N,
    int bm, int bn, uint32_t sbase, int tid)
{
    const int lane = tid & 31, w = tid >> 5;
    const int wm = w & 1, wn = w >> 1;

#pragma unroll
    for (int s = 0; s < 3; s++) {
        cp_stage64(A, B, bm, bn, sbase + s * STAGE64_B, tid, s);
        cp_commit();
    }

    float acc[2][2][4];
#pragma unroll
    for (int mb = 0; mb < 2; mb++)
#pragma unroll
        for (int nb = 0; nb < 2; nb++)
#pragma unroll
            for (int q = 0; q < 4; q++) acc[mb][nb][q] = 0.f;

    const int quad = lane >> 3, li = lane & 7;
    const uint32_t aAddr = sbase +
        (uint32_t)((wm * 32 + (quad & 1) * 8 + li) * APITCH + (quad >> 1) * 16);
    const uint32_t bAddr = sbase + ATILE64_B +
        (uint32_t)((wn * 16 + (quad >> 1) * 8 + li) * APITCH + (quad & 1) * 16);

#pragma unroll 4
    for (int i = 0; i < NIT; i++) {
        cp_wait<2>();
        __syncthreads();
        if (i + 3 < NIT)
            cp_stage64(A, B, bm, bn, sbase + ((i + 3) & 3) * STAGE64_B, tid, i + 3);
        cp_commit();

        const uint32_t sa = aAddr + (i & 3) * STAGE64_B;
        const uint32_t sb = bAddr + (i & 3) * STAGE64_B;
#pragma unroll
        for (int kh = 0; kh < 2; kh++) {
            uint32_t a[2][4];
            ldm_x4(a[0][0], a[0][1], a[0][2], a[0][3], sa + kh * 32);
            ldm_x4(a[1][0], a[1][1], a[1][2], a[1][3], sa + kh * 32 + 16 * APITCH);
            uint32_t b[2][2];
            ldm_x4(b[0][0], b[0][1], b[1][0], b[1][1], sb + kh * 32);
#pragma unroll
            for (int mb = 0; mb < 2; mb++)
#pragma unroll
                for (int nb = 0; nb < 2; nb++)
                    mma16816(acc[mb][nb], a[mb][0], a[mb][1], a[mb][2], a[mb][3],
                             b[nb][0], b[nb][1]);
        }
    }

    const int g = lane >> 2, t = lane & 3;
#pragma unroll
    for (int mb = 0; mb < 2; mb++) {
        const int r0 = bm + wm * 32 + mb * 16 + g;
#pragma unroll
        for (int nb = 0; nb < 2; nb++) {
            const int col = bn + wn * 16 + nb * 8 + t * 2;
            const float b0 = bias[col], b1 = bias[col + 1];
            *(__half2*)(Cs + (size_t)r0 * N + col) = __halves2half2(
                __float2half(acc[mb][nb][0] + b0), __float2half(acc[mb][nb][1] + b1));
            *(__half2*)(Cs + (size_t)(r0 + 8) * N + col) = __halves2half2(
                __float2half(acc[mb][nb][2] + b0), __float2half(acc[mb][nb][3] + b1));
        }
    }
}

// GEMM1 (64 CTAs) + convert W_hh (3072 rows)
__global__ void __launch_bounds__(256, 2)
gemm1_cvtWhh(const float* __restrict__ b_emb, const float* __restrict__ W_hh)
{
    extern __shared__ char sm[];
    const int blk = blockIdx.x, tid = threadIdx.x;
    if (blk < 64) {
        gemm64_body(g2_table, g2_Wemb, b_emb, g2_emb, H,
                    (blk >> 4) * 64, (blk & 15) * 64, smem_u32(sm), tid);
    } else {
        cvt_row(W_hh, g2_Whh, blk - 64, tid);
    }
}

// GEMM2 (192 CTAs) + convert W1, W2 (2048 rows)
__global__ void __launch_bounds__(256, 2)
gemm2_cvtW12(const float* __restrict__ b_ih,
             const float* __restrict__ W1, const float* __restrict__ W2)
{
    extern __shared__ char sm[];
    const int blk = blockIdx.x, tid = threadIdx.x;
    if (blk < 192) {
        gemm64_body(g2_emb, g2_Wih, b_ih, g2_gi, H3,
                    (blk / 48) * 64, (blk % 48) * 64, smem_u32(sm), tid);
    } else if (blk < 192 + 1024) {
        cvt_row(W1, g2_W1, blk - 192, tid);
    } else {
        cvt_row(W2, g2_W2, blk - 192 - 1024, tid);
    }
}

// GEMM4 (gh2, 192 CTAs)
__global__ void __launch_bounds__(256, 2)
gemm_hmma64(const __half* __restrict__ A, const __half* __restrict__ B,
            const float* __restrict__ bias, __half* __restrict__ Cs, int N)
{
    extern __shared__ char sm[];
    gemm64_body(A, B, bias, Cs, N,
                blockIdx.y * 64, blockIdx.x * 64, smem_u32(sm), threadIdx.x);
}

// ===================== launch 0: convert table/Wemb/Wih + gh1 GEMV + cnt reset =====================
#define CVT0_ROWS (256 + 1024 + 3072)   // 4352
__global__ void __launch_bounds__(256)
cvt_phase0(const float* __restrict__ table, const float* __restrict__ W_emb,
           const float* __restrict__ W_ih,
           const float* __restrict__ state, const float* __restrict__ W_hh,
           const float* __restrict__ b_hh)
{
    int row = blockIdx.x;
    int tid = threadIdx.x;
    if (row == 0 && tid == 0) g_cnt = 0;
    if (row >= CVT0_ROWS) {          // gh1 GEMV: 384 blocks x 8 warps
        int n = (row - CVT0_ROWS) * 8 + (tid >> 5);
        int lane = tid & 31;
        const float* w = W_hh + (size_t)n * H;
        float s = 0.f;
#pragma unroll
        for (int k = lane * 4; k < H; k += 128) {
            float4 wv = *(const float4*)(w + k);
            float4 xv = *(const float4*)(state + k);
            s = fmaf(wv.x, xv.x, s); s = fmaf(wv.y, xv.y, s);
            s = fmaf(wv.z, xv.z, s); s = fmaf(wv.w, xv.w, s);
        }
#pragma unroll
        for (int o = 16; o; o >>= 1) s += __shfl_xor_sync(0xffffffffu, s, o);
        if (lane == 0) g_gh1[n] = s + b_hh[n];
        return;
    }
    int r = row;
    if      (r < 256)            cvt_row(table, g2_table, r, tid);
    else if ((r -= 256) < 1024)  cvt_row(W_emb, g2_Wemb, r, tid);
    else                          cvt_row(W_ih, g2_Wih, r - 1024, tid);
}

// ===================== GRU combine =====================
__device__ __forceinline__ float4 ld4h(const __half* p) {
    uint2 u = *(const uint2*)p;                 // single 8B load
    float2 f0 = __half22float2(*(__half2*)&u.x);
    float2 f1 = __half22float2(*(__half2*)&u.y);
    return make_float4(f0.x, f0.y, f1.x, f1.y);
}
__device__ __forceinline__ float gru1(float ir, float iz, float inn,
                                      float hr, float hz, float hn, float h)
{
    float r = 1.f / (1.f + __expf(-(ir + hr)));
    float z = 1.f / (1.f + __expf(-(iz + hz)));
    float n = tanh_fast(fmaf(r, hn, inn));
    return fmaf(z, h - n, n);
}
__device__ __forceinline__ float4 gru4_comb(float4 ir, float4 iz, float4 inn,
                                            float4 hr, float4 hz, float4 hn, float4 hv)
{
    float4 o;
    o.x = gru1(ir.x, iz.x, inn.x, hr.x, hz.x, hn.x, hv.x);
    o.y = gru1(ir.y, iz.y, inn.y, hr.y, hz.y, hn.y, hv.y);
    o.z = gru1(ir.z, iz.z, inn.z, hr.z, hz.z, hn.z, hv.z);
    o.w = gru1(ir.w, iz.w, inn.w, hr.w, hz.w, hn.w, hv.w);
    return o;
}
__device__ __forceinline__ void cvt_store(__half* o, float4 v)
{
    *(__half2*)(o)     = __halves2half2(__float2half(v.x), __float2half(v.y));
    *(__half2*)(o + 2) = __halves2half2(__float2half(v.z), __float2half(v.w));
}

// h1: 512 blocks, 2 elems/thread
__global__ void gru_h1_kernel(const float* __restrict__ state)
{
    int v = blockIdx.x >> 1;
    int j = (blockIdx.x & 1) * 512 + threadIdx.x * 2;
    const __half* gi = g2_gi + (size_t)v * H3;
    float2 ir  = __half22float2(*(const __half2*)(gi + j));
    float2 iz  = __half22float2(*(const __half2*)(gi + H + j));
    float2 inn = __half22float2(*(const __half2*)(gi + 2 * H + j));
    float2 hr  = *(const float2*)(g_gh1 + j);
    float2 hz  = *(const float2*)(g_gh1 + H + j);
    float2 hn  = *(const float2*)(g_gh1 + 2 * H + j);
    float2 hv  = *(const float2*)(state + j);
    float o0 = gru1(ir.x, iz.x, inn.x, hr.x, hz.x, hn.x, hv.x);
    float o1 = gru1(ir.y, iz.y, inn.y, hr.y, hz.y, hn.y, hv.y);
    *(__half2*)(g2_h1 + (size_t)v * H + j) =
        __halves2half2(__float2half(o0), __float2half(o1));
}

__device__ __forceinline__ float4 gru4_hhh(const __half* gi, const __half* gh,
                                           const __half* h, int j)
{
    return gru4_comb(ld4h(gi + j), ld4h(gi + H + j), ld4h(gi + 2 * H + j),
                     ld4h(gh + j), ld4h(gh + H + j), ld4h(gh + 2 * H + j),
                     ld4h(h + j));
}

__global__ void gru_step2_all(const int* __restrict__ rel_tokens,
                              const int* __restrict__ attr_tokens)
{
    int blk = blockIdx.x;
    int j = threadIdx.x * 4;
    if (blk < NREL) {
        int t0 = rel_tokens[blk * 3 + 0];
        int t1 = rel_tokens[blk * 3 + 1];
        float4 o = gru4_hhh(g2_gi + (size_t)t1 * H3, g2_gh2 + (size_t)t0 * H3,
                            g2_h1 + (size_t)t0 * H, j);
        cvt_store(g2_h2rel + (size_t)blk * H + j, o);
    } else {
        int n = blk - NREL;
        int t0 = attr_tokens[n * 2 + 0];
        int t1 = attr_tokens[n * 2 + 1];
        float4 o = gru4_hhh(g2_gi + (size_t)t1 * H3, g2_gh2 + (size_t)t0 * H3,
                            g2_h1 + (size_t)t0 * H, j);
        cvt_store(g2_clause + (size_t)(NREL + n) * H + j, o);
    }
}

__global__ void gru_step3_kernel(const int* __restrict__ rel_tokens)
{
    int n  = blockIdx.x;
    int t2 = rel_tokens[n * 3 + 2];
    int j  = threadIdx.x * 4;
    float4 o = gru4_hhh(g2_gi + (size_t)t2 * H3, g2_gh3 + (size_t)n * H3,
                        g2_h2rel + (size_t)n * H, j);
    cvt_store(g2_clause + (size_t)n * H + j, o);
}

// ===================== launch =====================
extern "C" void kernel_launch(void* const* d_in, const int* in_sizes, int n_in,
                              void* d_out, int out_size)
{
    const float* state       = (const float*)d_in[0];
    const int*   rel_tokens  = (const int*)d_in[1];
    const int*   attr_tokens = (const int*)d_in[2];
    const float* table       = (const float*)d_in[3];
    const float* W_emb       = (const float*)d_in[4];
    const float* b_emb       = (const float*)d_in[5];
    const float* W_ih        = (const float*)d_in[6];
    const float* W_hh        = (const float*)d_in[7];
    const float* b_ih        = (const float*)d_in[8];
    const float* b_hh        = (const float*)d_in[9];
    const float* W1          = (const float*)d_in[10];
    const float* b1          = (const float*)d_in[11];
    const float* W2          = (const float*)d_in[12];
    const float* b2          = (const float*)d_in[13];
    const float* W3          = (const float*)d_in[14];
    const float* eps         = (const float*)d_in[16];
    float* out = (float*)d_out;

    __half *p2_h1, *p2_Whh, *p2_gh2;
    float *p_lpart;
    cudaGetSymbolAddress((void**)&p2_h1,   g2_h1);
    cudaGetSymbolAddress((void**)&p2_Whh,  g2_Whh);
    cudaGetSymbolAddress((void**)&p2_gh2,  g2_gh2);
    cudaGetSymbolAddress((void**)&p_lpart, g_lpart);

    cudaFuncSetAttribute(gemm_dual,
                         cudaFuncAttributeMaxDynamicSharedMemorySize, SMEM_DYN_H);
    cudaFuncSetAttribute(gemm_dual2,
                         cudaFuncAttributeMaxDynamicSharedMemorySize, SMEM_DYN_H);
    cudaFuncSetAttribute(gemm_logits_rel,
                         cudaFuncAttributeMaxDynamicSharedMemorySize, SMEM_DYN_H);

    // 0. convert table/Wemb/Wih + gh1 GEMV + counter reset
    cvt_phase0<<<CVT0_ROWS + 384, 256>>>(table, W_emb, W_ih, state, W_hh, b_hh);
    // 1. GEMM1 (emb, 64 CTAs) + cvt W_hh
    gemm1_cvtWhh<<<64 + 3072, 256, SMEM_DYN64>>>(b_emb, W_hh);
    // 2. GEMM2 (gi, 192 CTAs) + cvt W1/W2
    gemm2_cvtW12<<<192 + 2048, 256, SMEM_DYN64>>>(b_ih, W1, W2);
    // 3. h1_table (512 blocks)
    gru_h1_kernel<<<2 * V, 256>>>(state);
    // 4. gh2_table (192 CTAs)
    gemm_hmma64<<<dim3(H3 / 64, V / 64), 256, SMEM_DYN64>>>(
        p2_h1, p2_Whh, b_hh, p2_gh2, H3);
    // 5. merged step-2 (rel + attr)
    gru_step2_all<<<NREL + NATT, 256>>>(rel_tokens, attr_tokens);
    // 6. DUAL1: gh3 (768) + x1-attr (256) — BK=64 2-stage mainloop
    gemm_dual<<<1024, 256, SMEM_DYN_H>>>(b_hh, b1);
    // 7. rel step 3
    gru_step3_kernel<<<NREL, 256>>>(rel_tokens);
    // 8. DUAL2: x1-rel (256, drains first) + logits-attr (256)
    gemm_dual2<<<512, 256, SMEM_DYN_H>>>(b1, b2, W3, p_lpart);
    // 9. logits-rel (256) with fused last-CTA softmax + eps smoothing
    gemm_logits_rel<<<dim3(8, NREL / 128), 256, SMEM_DYN_H>>>(
        b2, W3, p_lpart, eps, out);
}